// round 1
// baseline (speedup 1.0000x reference)
#include <cuda_runtime.h>
#include <math.h>

#define BATCH  2
#define SEQ    2048
#define DIM    1024
#define HEADS  16
#define DHEAD  64
#define INNER  1024
#define MTOT   (BATCH*SEQ)
#define QSCALE 0.125f

// Scratch (device-global; no allocations allowed in kernel_launch)
__device__ float g_P[MTOT * INNER];   // qkv projection, first INNER cols (q=k=v source)
__device__ float g_O[MTOT * INNER];   // attention output, [b, n, h*DHEAD+d]

// ---------------------------------------------------------------------------
// Tiled fp32 GEMM: C[M,N] = A[M,K] @ B[K,N] (+ bias). BM=BN=128, BK=8,
// 256 threads, 8x8 per-thread tile. M,N multiples of 128; K multiple of 8.
// ---------------------------------------------------------------------------
__global__ __launch_bounds__(256) void gemm_bias_kernel(
    const float* __restrict__ A, const float* __restrict__ Bm,
    float* __restrict__ C, const float* __restrict__ bias,
    int K, int lda, int ldb, int ldc)
{
    __shared__ float As[8][128];
    __shared__ float Bs[8][128];

    const int tid  = threadIdx.x;
    const int brow = blockIdx.y * 128;
    const int bcol = blockIdx.x * 128;
    const int tr   = (tid >> 4) << 3;   // 0..120 step 8
    const int tc   = (tid & 15) << 3;   // 0..120 step 8

    float acc[8][8];
#pragma unroll
    for (int i = 0; i < 8; i++)
#pragma unroll
        for (int j = 0; j < 8; j++) acc[i][j] = 0.f;

    const int a_row = tid >> 1;            // 0..127
    const int a_col = (tid & 1) << 2;      // 0 or 4
    const int b_row = tid >> 5;            // 0..7
    const int b_col = (tid & 31) << 2;     // 0..124

    const float* Aptr = A  + (size_t)(brow + a_row) * lda + a_col;
    const float* Bptr = Bm + (size_t)b_row * ldb + bcol + b_col;

    for (int k0 = 0; k0 < K; k0 += 8) {
        float4 a4 = *(const float4*)(Aptr + k0);
        As[a_col + 0][a_row] = a4.x;
        As[a_col + 1][a_row] = a4.y;
        As[a_col + 2][a_row] = a4.z;
        As[a_col + 3][a_row] = a4.w;
        *(float4*)&Bs[b_row][b_col] = *(const float4*)(Bptr + (size_t)k0 * ldb);
        __syncthreads();

#pragma unroll
        for (int kk = 0; kk < 8; kk++) {
            float ar[8], br[8];
            *(float4*)(ar)     = *(float4*)&As[kk][tr];
            *(float4*)(ar + 4) = *(float4*)&As[kk][tr + 4];
            *(float4*)(br)     = *(float4*)&Bs[kk][tc];
            *(float4*)(br + 4) = *(float4*)&Bs[kk][tc + 4];
#pragma unroll
            for (int i = 0; i < 8; i++)
#pragma unroll
                for (int j = 0; j < 8; j++)
                    acc[i][j] = fmaf(ar[i], br[j], acc[i][j]);
        }
        __syncthreads();
    }

#pragma unroll
    for (int i = 0; i < 8; i++) {
        const size_t r = (size_t)(brow + tr + i) * ldc + bcol + tc;
#pragma unroll
        for (int j = 0; j < 8; j += 4) {
            float4 v;
            v.x = acc[i][j + 0];
            v.y = acc[i][j + 1];
            v.z = acc[i][j + 2];
            v.w = acc[i][j + 3];
            if (bias) {
                v.x += bias[bcol + tc + j + 0];
                v.y += bias[bcol + tc + j + 1];
                v.z += bias[bcol + tc + j + 2];
                v.w += bias[bcol + tc + j + 3];
            }
            *(float4*)&C[r + j] = v;
        }
    }
}

// ---------------------------------------------------------------------------
// Causal flash attention. Q=K=V = g_P slices (K,V unscaled; Q scaled here).
// One block per (q-tile of 64, head, batch). 256 threads, 4x4 per thread.
// K tile stored XOR-swizzled (d4 ^= key>>2): conflict-free for both QK^T
// (column reads) and PV (row reads), no padding -> exactly 48KB smem.
// ---------------------------------------------------------------------------
__global__ __launch_bounds__(256) void attn_kernel(
    const float* __restrict__ P, float* __restrict__ O)
{
    __shared__ float Qs[64][64];
    __shared__ float Ks[64][64];
    __shared__ float Ps[64][64];

    const int qt  = blockIdx.x;
    const int h   = blockIdx.y;
    const int b   = blockIdx.z;
    const int tid = threadIdx.x;
    const int tr  = tid >> 4;        // 0..15
    const int tc  = tid & 15;        // 0..15
    const int row0 = tr << 2;        // 4 rows per thread
    const int col0 = tc << 2;        // 4 cols per thread

    const float* base = P + (size_t)b * SEQ * INNER + h * DHEAD;

    // Load Q tile, scaled
#pragma unroll
    for (int it = 0; it < 4; it++) {
        int f4 = tid + it * 256;
        int r  = f4 >> 4;
        int d4 = f4 & 15;
        float4 q = *(const float4*)&base[(size_t)(qt * 64 + r) * INNER + (d4 << 2)];
        q.x *= QSCALE; q.y *= QSCALE; q.z *= QSCALE; q.w *= QSCALE;
        *(float4*)&Qs[r][d4 << 2] = q;
    }

    float m_i[4], l_i[4], acc[4][4];
#pragma unroll
    for (int rr = 0; rr < 4; rr++) {
        m_i[rr] = -1e30f;
        l_i[rr] = 0.f;
#pragma unroll
        for (int cc = 0; cc < 4; cc++) acc[rr][cc] = 0.f;
    }

    for (int kt = 0; kt <= qt; kt++) {
        __syncthreads();  // previous iter consumers done (also covers Qs on iter 0)

        // Load K tile (== V tile) with XOR swizzle on d4
#pragma unroll
        for (int it = 0; it < 4; it++) {
            int f4 = tid + it * 256;
            int r  = f4 >> 4;     // key index
            int d4 = f4 & 15;
            float4 kv = *(const float4*)&base[(size_t)(kt * 64 + r) * INNER + (d4 << 2)];
            *(float4*)&Ks[r][((d4 ^ (r >> 2)) & 15) << 2] = kv;
        }
        __syncthreads();

        // S = Q K^T (4x4 per thread)
        float s[4][4];
#pragma unroll
        for (int rr = 0; rr < 4; rr++)
#pragma unroll
            for (int cc = 0; cc < 4; cc++) s[rr][cc] = 0.f;

#pragma unroll
        for (int d4 = 0; d4 < 16; d4++) {
            float4 q4[4], k4[4];
#pragma unroll
            for (int rr = 0; rr < 4; rr++)
                q4[rr] = *(float4*)&Qs[row0 + rr][d4 << 2];
#pragma unroll
            for (int cc = 0; cc < 4; cc++) {
                int key = col0 + cc;
                k4[cc] = *(float4*)&Ks[key][((d4 ^ (key >> 2)) & 15) << 2];
            }
#pragma unroll
            for (int rr = 0; rr < 4; rr++)
#pragma unroll
                for (int cc = 0; cc < 4; cc++) {
                    s[rr][cc] = fmaf(q4[rr].x, k4[cc].x, s[rr][cc]);
                    s[rr][cc] = fmaf(q4[rr].y, k4[cc].y, s[rr][cc]);
                    s[rr][cc] = fmaf(q4[rr].z, k4[cc].z, s[rr][cc]);
                    s[rr][cc] = fmaf(q4[rr].w, k4[cc].w, s[rr][cc]);
                }
        }

        // Causal mask on diagonal tile
        if (kt == qt) {
#pragma unroll
            for (int rr = 0; rr < 4; rr++)
#pragma unroll
                for (int cc = 0; cc < 4; cc++)
                    if (col0 + cc > row0 + rr) s[rr][cc] = -1e30f;
        }

        // Online softmax update + stage probs to smem
#pragma unroll
        for (int rr = 0; rr < 4; rr++) {
            float mt = fmaxf(fmaxf(s[rr][0], s[rr][1]), fmaxf(s[rr][2], s[rr][3]));
#pragma unroll
            for (int off = 8; off; off >>= 1)
                mt = fmaxf(mt, __shfl_xor_sync(0xffffffffu, mt, off, 16));
            float mnew  = fmaxf(m_i[rr], mt);
            float alpha = __expf(m_i[rr] - mnew);
            m_i[rr] = mnew;
            float4 p;
            p.x = __expf(s[rr][0] - mnew);
            p.y = __expf(s[rr][1] - mnew);
            p.z = __expf(s[rr][2] - mnew);
            p.w = __expf(s[rr][3] - mnew);
            float ls = p.x + p.y + p.z + p.w;
#pragma unroll
            for (int off = 8; off; off >>= 1)
                ls += __shfl_xor_sync(0xffffffffu, ls, off, 16);
            l_i[rr] = l_i[rr] * alpha + ls;
            *(float4*)&Ps[row0 + rr][col0] = p;
#pragma unroll
            for (int cc = 0; cc < 4; cc++) acc[rr][cc] *= alpha;
        }
        __syncthreads();

        // O += P @ V (V rows == Ks rows, de-swizzled read)
#pragma unroll
        for (int j4 = 0; j4 < 16; j4++) {
            float pv[4][4];
#pragma unroll
            for (int rr = 0; rr < 4; rr++) {
                float4 p4 = *(float4*)&Ps[row0 + rr][j4 << 2];
                pv[rr][0] = p4.x; pv[rr][1] = p4.y; pv[rr][2] = p4.z; pv[rr][3] = p4.w;
            }
#pragma unroll
            for (int jj = 0; jj < 4; jj++) {
                int j = (j4 << 2) + jj;
                float4 v = *(float4*)&Ks[j][((tc ^ (j >> 2)) & 15) << 2];
                float vv[4] = {v.x, v.y, v.z, v.w};
#pragma unroll
                for (int rr = 0; rr < 4; rr++)
#pragma unroll
                    for (int cc = 0; cc < 4; cc++)
                        acc[rr][cc] = fmaf(pv[rr][jj], vv[cc], acc[rr][cc]);
            }
        }
    }

    // Normalize and write out: O[b, n, h*DHEAD + d]
#pragma unroll
    for (int rr = 0; rr < 4; rr++) {
        float inv = 1.f / l_i[rr];
        float4 o;
        o.x = acc[rr][0] * inv;
        o.y = acc[rr][1] * inv;
        o.z = acc[rr][2] * inv;
        o.w = acc[rr][3] * inv;
        size_t idx = ((size_t)b * SEQ + qt * 64 + row0 + rr) * INNER + h * DHEAD + col0;
        *(float4*)&O[idx] = o;
    }
}

extern "C" void kernel_launch(void* const* d_in, const int* in_sizes, int n_in,
                              void* d_out, int out_size)
{
    const float* x     = (const float*)d_in[0];   // [2, 2048, 1024]
    const float* w_qkv = (const float*)d_in[1];   // [1024, 3072] (only first 1024 cols used)
    const float* w_out = (const float*)d_in[2];   // [1024, 1024]
    const float* b_out = (const float*)d_in[3];   // [1024]
    float* out = (float*)d_out;                    // [2, 2048, 1024]

    float *P, *O;
    cudaGetSymbolAddress((void**)&P, g_P);
    cudaGetSymbolAddress((void**)&O, g_O);

    dim3 block(256);
    dim3 grid_g(INNER / 128, MTOT / 128);   // (8, 32)

    // 1) P = x @ w_qkv[:, :INNER]
    gemm_bias_kernel<<<grid_g, block>>>(x, w_qkv, P, nullptr,
                                        DIM, DIM, 3 * INNER, INNER);

    // 2) Causal flash attention with q=k=v=P (q scaled)
    dim3 grid_a(SEQ / 64, HEADS, BATCH);    // (32, 16, 2)
    attn_kernel<<<grid_a, block>>>(P, O);

    // 3) out = O @ w_out + b_out
    gemm_bias_kernel<<<grid_g, block>>>(O, w_out, out, b_out,
                                        INNER, INNER, DIM, DIM);
}

// round 3
// speedup vs baseline: 2.6499x; 2.6499x over previous
#include <cuda_runtime.h>
#include <cuda_fp16.h>
#include <stdint.h>
#include <math.h>

#define BATCH  2
#define SEQ    2048
#define DIM    1024
#define HEADS  16
#define DHEAD  64
#define INNER  1024
#define MTOT   (BATCH*SEQ)
#define SSCALE 0.125f

// ---------------------------------------------------------------------------
// Device-global scratch (hi/lo fp16 splits)
// ---------------------------------------------------------------------------
__device__ __half g_xh[MTOT * DIM],   g_xl[MTOT * DIM];
__device__ __half g_Ph[MTOT * INNER], g_Pl[MTOT * INNER];
__device__ __half g_Oh[MTOT * INNER], g_Ol[MTOT * INNER];
__device__ __half g_Wqh[INNER * DIM], g_Wql[INNER * DIM];   // w_qkv[:, :1024]^T
__device__ __half g_Woh[DIM * INNER], g_Wol[DIM * INNER];   // w_out^T

// ---------------------------------------------------------------------------
// PTX helpers (all family-portable: no 'a'-suffix features)
// ---------------------------------------------------------------------------
__device__ __forceinline__ uint32_t smem_u32(const void* p) {
    uint32_t a;
    asm("{ .reg .u64 t; cvta.to.shared.u64 t, %1; cvt.u32.u64 %0, t; }" : "=r"(a) : "l"(p));
    return a;
}

#define CP_ASYNC16(dst, src) \
    asm volatile("cp.async.cg.shared.global [%0], [%1], 16;" :: "r"(dst), "l"(src) : "memory")
#define CP_COMMIT() asm volatile("cp.async.commit_group;" ::: "memory")
#define CP_WAIT1()  asm volatile("cp.async.wait_group 1;"  ::: "memory")

#define LDSM4(r0, r1, r2, r3, a) \
    asm volatile("ldmatrix.sync.aligned.m8n8.x4.shared.b16 {%0,%1,%2,%3}, [%4];" \
        : "=r"(r0), "=r"(r1), "=r"(r2), "=r"(r3) : "r"(a))
#define LDSM4T(r0, r1, r2, r3, a) \
    asm volatile("ldmatrix.sync.aligned.m8n8.x4.trans.shared.b16 {%0,%1,%2,%3}, [%4];" \
        : "=r"(r0), "=r"(r1), "=r"(r2), "=r"(r3) : "r"(a))

#define MMA16816(d, a0, a1, a2, a3, b0, b1) \
    asm volatile("mma.sync.aligned.m16n8k16.row.col.f32.f16.f16.f32 " \
        "{%0,%1,%2,%3}, {%4,%5,%6,%7}, {%8,%9}, {%0,%1,%2,%3};" \
        : "+f"((d)[0]), "+f"((d)[1]), "+f"((d)[2]), "+f"((d)[3]) \
        : "r"(a0), "r"(a1), "r"(a2), "r"(a3), "r"(b0), "r"(b1))

__device__ __forceinline__ uint32_t packh2(float lo, float hi) {
    __half2 h = __floats2half2_rn(lo, hi);
    return *reinterpret_cast<uint32_t*>(&h);
}

// ---------------------------------------------------------------------------
// fp32 -> (fp16 hi, fp16 lo) elementwise split
// ---------------------------------------------------------------------------
__global__ __launch_bounds__(256) void split_kernel(
    const float* __restrict__ in, __half* __restrict__ hi, __half* __restrict__ lo, int n4)
{
    int i = blockIdx.x * 256 + threadIdx.x;
    if (i >= n4) return;
    float4 v = ((const float4*)in)[i];
    __half hx = __float2half_rn(v.x), hy = __float2half_rn(v.y);
    __half hz = __float2half_rn(v.z), hw = __float2half_rn(v.w);
    __half lx = __float2half_rn(v.x - __half2float(hx));
    __half ly = __float2half_rn(v.y - __half2float(hy));
    __half lz = __float2half_rn(v.z - __half2float(hz));
    __half lw = __float2half_rn(v.w - __half2float(hw));
    ((__half2*)hi)[2 * i]     = __halves2half2(hx, hy);
    ((__half2*)hi)[2 * i + 1] = __halves2half2(hz, hw);
    ((__half2*)lo)[2 * i]     = __halves2half2(lx, ly);
    ((__half2*)lo)[2 * i + 1] = __halves2half2(lz, lw);
}

// ---------------------------------------------------------------------------
// Transpose + split: dst[n][k] = src[k][n] (dst [1024][1024], hi/lo fp16)
// ---------------------------------------------------------------------------
__global__ __launch_bounds__(256) void transpose_split_kernel(
    const float* __restrict__ src, __half* __restrict__ dh, __half* __restrict__ dl, int ld_src)
{
    __shared__ float t[32][33];
    int bx = blockIdx.x * 32;   // n base
    int by = blockIdx.y * 32;   // k base
    int x = threadIdx.x, y0 = threadIdx.y;
#pragma unroll
    for (int i = 0; i < 32; i += 8)
        t[y0 + i][x] = src[(size_t)(by + y0 + i) * ld_src + bx + x];
    __syncthreads();
#pragma unroll
    for (int i = 0; i < 32; i += 8) {
        float v = t[x][y0 + i];
        __half h = __float2half_rn(v);
        __half l = __float2half_rn(v - __half2float(h));
        size_t idx = (size_t)(bx + y0 + i) * 1024 + by + x;
        dh[idx] = h;
        dl[idx] = l;
    }
}

// ---------------------------------------------------------------------------
// Split-fp16 MMA GEMM: C[M,N] = (Ah+Al)[M,K] @ (Bh+Bl)^T  (B stored [N][K])
// BM=BN=128, BK=32, 2-stage cp.async, 256 threads (8 warps: 4m x 2n).
// Output: fp32 (+bias) OR fp16 hi/lo pair.
// smem tile rows padded to 40 halfs (80B) -> conflict-free ldmatrix.
// ---------------------------------------------------------------------------
#define G_TILE_B  10240               // 128*40*2
#define G_STAGE_B (4 * G_TILE_B)      // Ah, Al, Bh, Bl
#define G_SMEM_B  (2 * G_STAGE_B)     // 81920

__global__ __launch_bounds__(256) void gemm_split_kernel(
    const __half* __restrict__ Ah, const __half* __restrict__ Al,
    const __half* __restrict__ Bh, const __half* __restrict__ Bl,
    float* __restrict__ Cf, const float* __restrict__ bias,
    __half* __restrict__ Ch, __half* __restrict__ Cl,
    int K, int ldc)
{
    extern __shared__ char smem[];
    const uint32_t sb = smem_u32(smem);
    const int tid = threadIdx.x;
    const int lane = tid & 31, wid = tid >> 5;
    const int g = lane >> 2, q = lane & 3;
    const int ml = lane >> 3, rl = lane & 7;
    const int wm = wid >> 1, wn = wid & 1;
    const int brow = blockIdx.y * 128;
    const int bcol = blockIdx.x * 128;

    float acc[2][8][4];
#pragma unroll
    for (int a = 0; a < 2; a++)
#pragma unroll
        for (int b = 0; b < 8; b++)
#pragma unroll
            for (int c = 0; c < 4; c++) acc[a][b][c] = 0.f;

#define G_LOAD(kt_, s_) do {                                                       \
    int _k0 = (kt_) << 5;                                                          \
    _Pragma("unroll")                                                              \
    for (int _i = 0; _i < 8; _i++) {                                               \
        int _id = tid + (_i << 8);                                                 \
        int _t = _id >> 9, _row = (_id >> 2) & 127, _c = _id & 3;                  \
        const __half* _src = (_t == 0) ? Ah : (_t == 1) ? Al : (_t == 2) ? Bh : Bl;\
        int _grow = ((_t < 2) ? brow : bcol) + _row;                               \
        const __half* _gp = _src + (size_t)_grow * K + _k0 + (_c << 3);            \
        uint32_t _dst = sb + (s_) * G_STAGE_B + _t * G_TILE_B + _row * 80 + (_c << 4); \
        CP_ASYNC16(_dst, _gp);                                                     \
    }                                                                              \
} while (0)

    G_LOAD(0, 0); CP_COMMIT();
    G_LOAD(1, 1); CP_COMMIT();

    const int nkt = K >> 5;
    for (int kt = 0; kt < nkt; kt++) {
        CP_WAIT1();
        __syncthreads();
        const uint32_t base = sb + (kt & 1) * G_STAGE_B;

#pragma unroll
        for (int ks = 0; ks < 2; ks++) {
            const int kk = ks << 4;
            uint32_t ah[2][4], al[2][4];
#pragma unroll
            for (int mt = 0; mt < 2; mt++) {
                int arow = wm * 32 + mt * 16 + (ml & 1) * 8 + rl;
                int acol = kk + (ml >> 1) * 8;
                uint32_t off = (uint32_t)(arow * 40 + acol) * 2;
                LDSM4(ah[mt][0], ah[mt][1], ah[mt][2], ah[mt][3], base + off);
                LDSM4(al[mt][0], al[mt][1], al[mt][2], al[mt][3], base + G_TILE_B + off);
            }
#pragma unroll
            for (int nt2 = 0; nt2 < 4; nt2++) {
                int n0 = wn * 64 + nt2 * 16;
                int br = n0 + (ml >> 1) * 8 + rl;
                int bc = kk + (ml & 1) * 8;
                uint32_t off = (uint32_t)(br * 40 + bc) * 2;
                uint32_t bh0, bh1, bh2, bh3, bl0, bl1, bl2, bl3;
                LDSM4(bh0, bh1, bh2, bh3, base + 2 * G_TILE_B + off);
                LDSM4(bl0, bl1, bl2, bl3, base + 3 * G_TILE_B + off);
#pragma unroll
                for (int mt = 0; mt < 2; mt++) {
                    MMA16816(acc[mt][2 * nt2],     ah[mt][0], ah[mt][1], ah[mt][2], ah[mt][3], bh0, bh1);
                    MMA16816(acc[mt][2 * nt2],     ah[mt][0], ah[mt][1], ah[mt][2], ah[mt][3], bl0, bl1);
                    MMA16816(acc[mt][2 * nt2],     al[mt][0], al[mt][1], al[mt][2], al[mt][3], bh0, bh1);
                    MMA16816(acc[mt][2 * nt2 + 1], ah[mt][0], ah[mt][1], ah[mt][2], ah[mt][3], bh2, bh3);
                    MMA16816(acc[mt][2 * nt2 + 1], ah[mt][0], ah[mt][1], ah[mt][2], ah[mt][3], bl2, bl3);
                    MMA16816(acc[mt][2 * nt2 + 1], al[mt][0], al[mt][1], al[mt][2], al[mt][3], bh2, bh3);
                }
            }
        }
        __syncthreads();
        if (kt + 2 < nkt) G_LOAD(kt + 2, kt & 1);
        CP_COMMIT();
    }

    // Epilogue
#pragma unroll
    for (int mt = 0; mt < 2; mt++) {
#pragma unroll
        for (int nt = 0; nt < 8; nt++) {
            int row = brow + wm * 32 + mt * 16 + g;
            int col = bcol + wn * 64 + nt * 8 + 2 * q;
            float c0 = acc[mt][nt][0], c1 = acc[mt][nt][1];
            float c2 = acc[mt][nt][2], c3 = acc[mt][nt][3];
            if (Cf) {
                if (bias) { c0 += bias[col]; c1 += bias[col + 1]; c2 += bias[col]; c3 += bias[col + 1]; }
                float2 v0 = {c0, c1}, v1 = {c2, c3};
                *(float2*)&Cf[(size_t)row * ldc + col] = v0;
                *(float2*)&Cf[(size_t)(row + 8) * ldc + col] = v1;
            } else {
                __half h0 = __float2half_rn(c0), h1 = __float2half_rn(c1);
                __half h2 = __float2half_rn(c2), h3 = __float2half_rn(c3);
                __half l0 = __float2half_rn(c0 - __half2float(h0));
                __half l1 = __float2half_rn(c1 - __half2float(h1));
                __half l2 = __float2half_rn(c2 - __half2float(h2));
                __half l3 = __float2half_rn(c3 - __half2float(h3));
                *(__half2*)&Ch[(size_t)row * ldc + col]       = __halves2half2(h0, h1);
                *(__half2*)&Ch[(size_t)(row + 8) * ldc + col] = __halves2half2(h2, h3);
                *(__half2*)&Cl[(size_t)row * ldc + col]       = __halves2half2(l0, l1);
                *(__half2*)&Cl[(size_t)(row + 8) * ldc + col] = __halves2half2(l2, l3);
            }
        }
    }
#undef G_LOAD
}

// ---------------------------------------------------------------------------
// Causal flash attention, split-fp16 MMA. Q=K=V = (Ph + Pl) head slices.
// Block: 128 q-rows x (64-key tiles), 8 warps (16 rows each), 256 threads.
// smem: Qh/Ql [128][72], K stages [2][h|l][64][72] (144B rows, conflict-free).
// ---------------------------------------------------------------------------
#define A_QTILE_B 18432              // 128*72*2
#define A_KTILE_B 9216               // 64*72*2
#define A_KOFF    (2 * A_QTILE_B)    // 36864
#define A_SMEM_B  (A_KOFF + 4 * A_KTILE_B)   // 73728

__global__ __launch_bounds__(256) void attn_mma_kernel(
    const __half* __restrict__ Ph, const __half* __restrict__ Pl,
    __half* __restrict__ Oh, __half* __restrict__ Ol)
{
    extern __shared__ char smem[];
    const uint32_t sb = smem_u32(smem);
    const int qt = blockIdx.x, h = blockIdx.y, b = blockIdx.z;
    const int tid = threadIdx.x;
    const int lane = tid & 31, wid = tid >> 5;
    const int g = lane >> 2, q = lane & 3;
    const int ml = lane >> 3, rl = lane & 7;

    const size_t pbase = (size_t)b * SEQ * INNER + h * DHEAD;

    // ---- prologue loads: Q (both tiles) + K stages 0,1 ----
#pragma unroll
    for (int i = 0; i < 8; i++) {     // Q: 2 tiles * 128 rows * 8 chunks = 2048
        int id = tid + (i << 8);
        int t = id >> 10, row = (id >> 3) & 127, c = id & 7;
        const __half* src = t ? Pl : Ph;
        const __half* gp = src + pbase + (size_t)(qt * 128 + row) * INNER + (c << 3);
        uint32_t dst = sb + t * A_QTILE_B + row * 144 + (c << 4);
        CP_ASYNC16(dst, gp);
    }
    CP_COMMIT();

#define A_LOADK(kt_, s_) do {                                                      \
    _Pragma("unroll")                                                              \
    for (int _i = 0; _i < 4; _i++) {  /* 2 tiles * 64 rows * 8 chunks = 1024 */    \
        int _id = tid + (_i << 8);                                                 \
        int _t = _id >> 9, _row = (_id >> 3) & 63, _c = _id & 7;                   \
        const __half* _src = _t ? Pl : Ph;                                         \
        const __half* _gp = _src + pbase + (size_t)((kt_) * 64 + _row) * INNER + (_c << 3); \
        uint32_t _dst = sb + A_KOFF + ((s_) * 2 + _t) * A_KTILE_B + _row * 144 + (_c << 4); \
        CP_ASYNC16(_dst, _gp);                                                     \
    }                                                                              \
} while (0)

    const int ntiles = 2 * qt + 2;
    A_LOADK(0, 0); CP_COMMIT();
    A_LOADK(1, 1); CP_COMMIT();

    CP_WAIT1();          // Q + K0 landed
    __syncthreads();

    // ---- Q fragments (held in regs for whole kernel) ----
    uint32_t qh[4][4], ql[4][4];
#pragma unroll
    for (int ks = 0; ks < 4; ks++) {
        int qr = wid * 16 + (ml & 1) * 8 + rl;
        int qc = ks * 16 + (ml >> 1) * 8;
        uint32_t off = (uint32_t)(qr * 72 + qc) * 2;
        LDSM4(qh[ks][0], qh[ks][1], qh[ks][2], qh[ks][3], sb + off);
        LDSM4(ql[ks][0], ql[ks][1], ql[ks][2], ql[ks][3], sb + A_QTILE_B + off);
    }

    float o[8][4];
#pragma unroll
    for (int nt = 0; nt < 8; nt++)
#pragma unroll
        for (int e = 0; e < 4; e++) o[nt][e] = 0.f;
    float m_i[2] = {-1e30f, -1e30f};
    float l_i[2] = {0.f, 0.f};

    for (int kt = 0; kt < ntiles; kt++) {
        if (kt > 0) { CP_WAIT1(); __syncthreads(); }
        const uint32_t kh_base = sb + A_KOFF + ((kt & 1) * 2) * A_KTILE_B;
        const uint32_t kl_base = kh_base + A_KTILE_B;

        // ---- S = (Qh+Ql)(Kh+Kl)^T (3-term split) ----
        float s[8][4];
#pragma unroll
        for (int nt = 0; nt < 8; nt++)
#pragma unroll
            for (int e = 0; e < 4; e++) s[nt][e] = 0.f;

#pragma unroll
        for (int ks = 0; ks < 4; ks++) {
            const int kk = ks << 4;
#pragma unroll
            for (int nt2 = 0; nt2 < 4; nt2++) {
                int n0 = nt2 * 16;
                int br = n0 + (ml >> 1) * 8 + rl;
                int bc = kk + (ml & 1) * 8;
                uint32_t off = (uint32_t)(br * 72 + bc) * 2;
                uint32_t bh0, bh1, bh2, bh3, bl0, bl1, bl2, bl3;
                LDSM4(bh0, bh1, bh2, bh3, kh_base + off);
                LDSM4(bl0, bl1, bl2, bl3, kl_base + off);
                MMA16816(s[2 * nt2],     qh[ks][0], qh[ks][1], qh[ks][2], qh[ks][3], bh0, bh1);
                MMA16816(s[2 * nt2],     qh[ks][0], qh[ks][1], qh[ks][2], qh[ks][3], bl0, bl1);
                MMA16816(s[2 * nt2],     ql[ks][0], ql[ks][1], ql[ks][2], ql[ks][3], bh0, bh1);
                MMA16816(s[2 * nt2 + 1], qh[ks][0], qh[ks][1], qh[ks][2], qh[ks][3], bh2, bh3);
                MMA16816(s[2 * nt2 + 1], qh[ks][0], qh[ks][1], qh[ks][2], qh[ks][3], bl2, bl3);
                MMA16816(s[2 * nt2 + 1], ql[ks][0], ql[ks][1], ql[ks][2], ql[ks][3], bh2, bh3);
            }
        }

        // ---- online softmax ----
        const bool domask = (kt >= 2 * qt);
        const int kbase = kt * 64;
#pragma unroll
        for (int rr = 0; rr < 2; rr++) {
            const int qrow = qt * 128 + wid * 16 + g + rr * 8;
            float mt = -1e30f;
#pragma unroll
            for (int nt = 0; nt < 8; nt++)
#pragma unroll
                for (int e = 0; e < 2; e++) {
                    float v = s[nt][rr * 2 + e] * SSCALE;
                    if (domask && (kbase + nt * 8 + 2 * q + e > qrow)) v = -1e30f;
                    s[nt][rr * 2 + e] = v;
                    mt = fmaxf(mt, v);
                }
            mt = fmaxf(mt, __shfl_xor_sync(0xffffffffu, mt, 1, 4));
            mt = fmaxf(mt, __shfl_xor_sync(0xffffffffu, mt, 2, 4));
            float mnew = fmaxf(m_i[rr], mt);
            float alpha = __expf(m_i[rr] - mnew);
            m_i[rr] = mnew;
            float ls = 0.f;
#pragma unroll
            for (int nt = 0; nt < 8; nt++)
#pragma unroll
                for (int e = 0; e < 2; e++) {
                    float p = __expf(s[nt][rr * 2 + e] - mnew);
                    s[nt][rr * 2 + e] = p;
                    ls += p;
                }
            ls += __shfl_xor_sync(0xffffffffu, ls, 1, 4);
            ls += __shfl_xor_sync(0xffffffffu, ls, 2, 4);
            l_i[rr] = l_i[rr] * alpha + ls;
#pragma unroll
            for (int nt = 0; nt < 8; nt++)
#pragma unroll
                for (int e = 0; e < 2; e++) o[nt][rr * 2 + e] *= alpha;
        }

        // ---- pack probs into A fragments ----
        uint32_t pa[4][4];
#pragma unroll
        for (int ks = 0; ks < 4; ks++) {
            pa[ks][0] = packh2(s[2 * ks][0],     s[2 * ks][1]);
            pa[ks][1] = packh2(s[2 * ks][2],     s[2 * ks][3]);
            pa[ks][2] = packh2(s[2 * ks + 1][0], s[2 * ks + 1][1]);
            pa[ks][3] = packh2(s[2 * ks + 1][2], s[2 * ks + 1][3]);
        }

        // ---- O += P (Vh + Vl), V via ldmatrix.trans from same K tiles ----
#pragma unroll
        for (int ks = 0; ks < 4; ks++) {
#pragma unroll
            for (int nt2 = 0; nt2 < 4; nt2++) {
                int vrow = ks * 16 + (ml & 1) * 8 + rl;
                int vcol = nt2 * 16 + (ml >> 1) * 8;
                uint32_t off = (uint32_t)(vrow * 72 + vcol) * 2;
                uint32_t vh0, vh1, vh2, vh3, vl0, vl1, vl2, vl3;
                LDSM4T(vh0, vh1, vh2, vh3, kh_base + off);
                LDSM4T(vl0, vl1, vl2, vl3, kl_base + off);
                MMA16816(o[2 * nt2],     pa[ks][0], pa[ks][1], pa[ks][2], pa[ks][3], vh0, vh1);
                MMA16816(o[2 * nt2],     pa[ks][0], pa[ks][1], pa[ks][2], pa[ks][3], vl0, vl1);
                MMA16816(o[2 * nt2 + 1], pa[ks][0], pa[ks][1], pa[ks][2], pa[ks][3], vh2, vh3);
                MMA16816(o[2 * nt2 + 1], pa[ks][0], pa[ks][1], pa[ks][2], pa[ks][3], vl2, vl3);
            }
        }

        __syncthreads();
        if (kt + 2 < ntiles) A_LOADK(kt + 2, kt & 1);
        CP_COMMIT();
    }

    // ---- normalize + split-store O ----
#pragma unroll
    for (int rr = 0; rr < 2; rr++) {
        const float inv = 1.f / l_i[rr];
        const size_t row = (size_t)b * SEQ + qt * 128 + wid * 16 + g + rr * 8;
#pragma unroll
        for (int nt = 0; nt < 8; nt++) {
            float v0 = o[nt][rr * 2 + 0] * inv;
            float v1 = o[nt][rr * 2 + 1] * inv;
            __half h0 = __float2half_rn(v0), h1 = __float2half_rn(v1);
            __half l0 = __float2half_rn(v0 - __half2float(h0));
            __half l1 = __float2half_rn(v1 - __half2float(h1));
            size_t idx = row * INNER + h * DHEAD + nt * 8 + 2 * q;
            *(__half2*)&Oh[idx] = __halves2half2(h0, h1);
            *(__half2*)&Ol[idx] = __halves2half2(l0, l1);
        }
    }
#undef A_LOADK
}

// ---------------------------------------------------------------------------
extern "C" void kernel_launch(void* const* d_in, const int* in_sizes, int n_in,
                              void* d_out, int out_size)
{
    const float* x     = (const float*)d_in[0];
    const float* w_qkv = (const float*)d_in[1];   // [1024, 3072]
    const float* w_out = (const float*)d_in[2];   // [1024, 1024]
    const float* b_out = (const float*)d_in[3];
    float* out = (float*)d_out;

    __half *xh, *xl, *Ph, *Pl, *Ohp, *Olp, *Wqh, *Wql, *Woh, *Wol;
    cudaGetSymbolAddress((void**)&xh, g_xh);   cudaGetSymbolAddress((void**)&xl, g_xl);
    cudaGetSymbolAddress((void**)&Ph, g_Ph);   cudaGetSymbolAddress((void**)&Pl, g_Pl);
    cudaGetSymbolAddress((void**)&Ohp, g_Oh);  cudaGetSymbolAddress((void**)&Olp, g_Ol);
    cudaGetSymbolAddress((void**)&Wqh, g_Wqh); cudaGetSymbolAddress((void**)&Wql, g_Wql);
    cudaGetSymbolAddress((void**)&Woh, g_Woh); cudaGetSymbolAddress((void**)&Wol, g_Wol);

    static int configured = 0;
    if (!configured) {
        cudaFuncSetAttribute(gemm_split_kernel,
                             cudaFuncAttributeMaxDynamicSharedMemorySize, G_SMEM_B);
        cudaFuncSetAttribute(attn_mma_kernel,
                             cudaFuncAttributeMaxDynamicSharedMemorySize, A_SMEM_B);
        configured = 1;
    }

    // 0) splits + transposed/split weights
    split_kernel<<<(MTOT * DIM / 4 + 255) / 256, 256>>>(x, xh, xl, MTOT * DIM / 4);
    dim3 tblk(32, 8), tgrd(32, 32);
    transpose_split_kernel<<<tgrd, tblk>>>(w_qkv, Wqh, Wql, 3 * INNER);
    transpose_split_kernel<<<tgrd, tblk>>>(w_out, Woh, Wol, DIM);

    // 1) P = x @ w_qkv[:, :INNER]  (fp16 hi/lo out)
    dim3 gblk(256), ggrd(INNER / 128, MTOT / 128);
    gemm_split_kernel<<<ggrd, gblk, G_SMEM_B>>>(xh, xl, Wqh, Wql,
                                                nullptr, nullptr, Ph, Pl, DIM, INNER);

    // 2) causal attention, q=k=v=P
    dim3 ablk(256), agrd(SEQ / 128, HEADS, BATCH);
    attn_mma_kernel<<<agrd, ablk, A_SMEM_B>>>(Ph, Pl, Ohp, Olp);

    // 3) out = O @ w_out + b_out  (fp32 out)
    gemm_split_kernel<<<ggrd, gblk, G_SMEM_B>>>(Ohp, Olp, Woh, Wol,
                                                out, b_out, nullptr, nullptr, INNER, DIM);
}

// round 4
// speedup vs baseline: 2.6955x; 1.0172x over previous
#include <cuda_runtime.h>
#include <cuda_fp16.h>
#include <stdint.h>
#include <math.h>

#define BATCH  2
#define SEQ    2048
#define DIM    1024
#define HEADS  16
#define DHEAD  64
#define INNER  1024
#define MTOT   (BATCH*SEQ)
#define SSCALE 0.125f

// ---------------------------------------------------------------------------
// Device-global scratch (hi/lo fp16 splits)
// ---------------------------------------------------------------------------
__device__ __half g_xh[MTOT * DIM],   g_xl[MTOT * DIM];
__device__ __half g_Ph[MTOT * INNER], g_Pl[MTOT * INNER];
__device__ __half g_Oh[MTOT * INNER], g_Ol[MTOT * INNER];
__device__ __half g_Wqh[INNER * DIM], g_Wql[INNER * DIM];   // w_qkv[:, :1024]^T
__device__ __half g_Woh[DIM * INNER], g_Wol[DIM * INNER];   // w_out^T

// ---------------------------------------------------------------------------
// PTX helpers (family-portable only)
// ---------------------------------------------------------------------------
__device__ __forceinline__ uint32_t smem_u32(const void* p) {
    uint32_t a;
    asm("{ .reg .u64 t; cvta.to.shared.u64 t, %1; cvt.u32.u64 %0, t; }" : "=r"(a) : "l"(p));
    return a;
}

#define CP_ASYNC16(dst, src) \
    asm volatile("cp.async.cg.shared.global [%0], [%1], 16;" :: "r"(dst), "l"(src) : "memory")
#define CP_COMMIT() asm volatile("cp.async.commit_group;" ::: "memory")
#define CP_WAIT1()  asm volatile("cp.async.wait_group 1;"  ::: "memory")

#define LDSM4(r0, r1, r2, r3, a) \
    asm volatile("ldmatrix.sync.aligned.m8n8.x4.shared.b16 {%0,%1,%2,%3}, [%4];" \
        : "=r"(r0), "=r"(r1), "=r"(r2), "=r"(r3) : "r"(a))
#define LDSM4T(r0, r1, r2, r3, a) \
    asm volatile("ldmatrix.sync.aligned.m8n8.x4.trans.shared.b16 {%0,%1,%2,%3}, [%4];" \
        : "=r"(r0), "=r"(r1), "=r"(r2), "=r"(r3) : "r"(a))

#define MMA16816(d, a0, a1, a2, a3, b0, b1) \
    asm volatile("mma.sync.aligned.m16n8k16.row.col.f32.f16.f16.f32 " \
        "{%0,%1,%2,%3}, {%4,%5,%6,%7}, {%8,%9}, {%0,%1,%2,%3};" \
        : "+f"((d)[0]), "+f"((d)[1]), "+f"((d)[2]), "+f"((d)[3]) \
        : "r"(a0), "r"(a1), "r"(a2), "r"(a3), "r"(b0), "r"(b1))

__device__ __forceinline__ uint32_t packh2(float lo, float hi) {
    __half2 h = __floats2half2_rn(lo, hi);
    return *reinterpret_cast<uint32_t*>(&h);
}

// ---------------------------------------------------------------------------
// fp32 -> (fp16 hi, fp16 lo) split
// ---------------------------------------------------------------------------
__global__ __launch_bounds__(256) void split_kernel(
    const float* __restrict__ in, __half* __restrict__ hi, __half* __restrict__ lo, int n4)
{
    int i = blockIdx.x * 256 + threadIdx.x;
    if (i >= n4) return;
    float4 v = ((const float4*)in)[i];
    __half hx = __float2half_rn(v.x), hy = __float2half_rn(v.y);
    __half hz = __float2half_rn(v.z), hw = __float2half_rn(v.w);
    __half lx = __float2half_rn(v.x - __half2float(hx));
    __half ly = __float2half_rn(v.y - __half2float(hy));
    __half lz = __float2half_rn(v.z - __half2float(hz));
    __half lw = __float2half_rn(v.w - __half2float(hw));
    ((__half2*)hi)[2 * i]     = __halves2half2(hx, hy);
    ((__half2*)hi)[2 * i + 1] = __halves2half2(hz, hw);
    ((__half2*)lo)[2 * i]     = __halves2half2(lx, ly);
    ((__half2*)lo)[2 * i + 1] = __halves2half2(lz, lw);
}

// ---------------------------------------------------------------------------
// Transpose + split
// ---------------------------------------------------------------------------
__global__ __launch_bounds__(256) void transpose_split_kernel(
    const float* __restrict__ src, __half* __restrict__ dh, __half* __restrict__ dl, int ld_src)
{
    __shared__ float t[32][33];
    int bx = blockIdx.x * 32;
    int by = blockIdx.y * 32;
    int x = threadIdx.x, y0 = threadIdx.y;
#pragma unroll
    for (int i = 0; i < 32; i += 8)
        t[y0 + i][x] = src[(size_t)(by + y0 + i) * ld_src + bx + x];
    __syncthreads();
#pragma unroll
    for (int i = 0; i < 32; i += 8) {
        float v = t[x][y0 + i];
        __half h = __float2half_rn(v);
        __half l = __float2half_rn(v - __half2float(h));
        size_t idx = (size_t)(bx + y0 + i) * 1024 + by + x;
        dh[idx] = h;
        dl[idx] = l;
    }
}

// ---------------------------------------------------------------------------
// Split-fp16 MMA GEMM: C[M,N] = (Ah+Al)[M,K] @ (Bh+Bl)^T  (B stored [N][K])
// BM=128, BN=64, BK=32, 2-stage, 256 thr (8 warps: 4m x 2n), 2 CTAs/SM.
// smem rows padded to 40 halfs (80B).
// ---------------------------------------------------------------------------
#define G_ATILE_B 10240               // 128*40*2
#define G_BTILE_B 5120                // 64*40*2
#define G_STAGE_B (2 * G_ATILE_B + 2 * G_BTILE_B)   // 30720
#define G_SMEM_B  (2 * G_STAGE_B)                    // 61440

__global__ __launch_bounds__(256, 2) void gemm_split_kernel(
    const __half* __restrict__ Ah, const __half* __restrict__ Al,
    const __half* __restrict__ Bh, const __half* __restrict__ Bl,
    float* __restrict__ Cf, const float* __restrict__ bias,
    __half* __restrict__ Ch, __half* __restrict__ Cl,
    int K, int ldc)
{
    extern __shared__ char smem[];
    const uint32_t sb = smem_u32(smem);
    const int tid = threadIdx.x;
    const int lane = tid & 31, wid = tid >> 5;
    const int g = lane >> 2, q = lane & 3;
    const int ml = lane >> 3, rl = lane & 7;
    const int wm = wid >> 1, wn = wid & 1;
    const int brow = blockIdx.y * 128;
    const int bcol = blockIdx.x * 64;

    float acc[2][4][4];
#pragma unroll
    for (int a = 0; a < 2; a++)
#pragma unroll
        for (int b = 0; b < 4; b++)
#pragma unroll
            for (int c = 0; c < 4; c++) acc[a][b][c] = 0.f;

    // per stage: A 2*512 chunks, B 2*256 chunks = 1536 -> 6 per thread
#define G_LOAD(kt_, s_) do {                                                       \
    int _k0 = (kt_) << 5;                                                          \
    _Pragma("unroll")                                                              \
    for (int _i = 0; _i < 6; _i++) {                                               \
        int _id = tid + (_i << 8);                                                 \
        const __half* _src; int _row, _c; uint32_t _toff;                          \
        if (_id < 1024) {                                                          \
            int _t = _id >> 9; _row = (_id >> 2) & 127; _c = _id & 3;              \
            _src = _t ? Al : Ah; _toff = _t * G_ATILE_B;                           \
            _src += (size_t)(brow + _row) * K;                                     \
        } else {                                                                   \
            int _ib = _id - 1024;                                                  \
            int _t = _ib >> 8; _row = (_ib >> 2) & 63; _c = _ib & 3;               \
            _src = _t ? Bl : Bh; _toff = 2 * G_ATILE_B + _t * G_BTILE_B;           \
            _src += (size_t)(bcol + _row) * K;                                     \
        }                                                                          \
        uint32_t _dst = sb + (s_) * G_STAGE_B + _toff + _row * 80 + (_c << 4);     \
        CP_ASYNC16(_dst, _src + _k0 + (_c << 3));                                  \
    }                                                                              \
} while (0)

    G_LOAD(0, 0); CP_COMMIT();
    G_LOAD(1, 1); CP_COMMIT();

    const int nkt = K >> 5;
    for (int kt = 0; kt < nkt; kt++) {
        CP_WAIT1();
        __syncthreads();
        const uint32_t base = sb + (kt & 1) * G_STAGE_B;

#pragma unroll
        for (int ks = 0; ks < 2; ks++) {
            const int kk = ks << 4;
            uint32_t ah[2][4], al[2][4];
#pragma unroll
            for (int mt = 0; mt < 2; mt++) {
                int arow = wm * 32 + mt * 16 + (ml & 1) * 8 + rl;
                int acol = kk + (ml >> 1) * 8;
                uint32_t off = (uint32_t)(arow * 40 + acol) * 2;
                LDSM4(ah[mt][0], ah[mt][1], ah[mt][2], ah[mt][3], base + off);
                LDSM4(al[mt][0], al[mt][1], al[mt][2], al[mt][3], base + G_ATILE_B + off);
            }
#pragma unroll
            for (int nt2 = 0; nt2 < 2; nt2++) {
                int br = wn * 32 + nt2 * 16 + (ml >> 1) * 8 + rl;
                int bc = kk + (ml & 1) * 8;
                uint32_t off = (uint32_t)(br * 40 + bc) * 2;
                uint32_t bh0, bh1, bh2, bh3, bl0, bl1, bl2, bl3;
                LDSM4(bh0, bh1, bh2, bh3, base + 2 * G_ATILE_B + off);
                LDSM4(bl0, bl1, bl2, bl3, base + 2 * G_ATILE_B + G_BTILE_B + off);
#pragma unroll
                for (int mt = 0; mt < 2; mt++) {
                    MMA16816(acc[mt][2 * nt2],     ah[mt][0], ah[mt][1], ah[mt][2], ah[mt][3], bh0, bh1);
                    MMA16816(acc[mt][2 * nt2],     ah[mt][0], ah[mt][1], ah[mt][2], ah[mt][3], bl0, bl1);
                    MMA16816(acc[mt][2 * nt2],     al[mt][0], al[mt][1], al[mt][2], al[mt][3], bh0, bh1);
                    MMA16816(acc[mt][2 * nt2 + 1], ah[mt][0], ah[mt][1], ah[mt][2], ah[mt][3], bh2, bh3);
                    MMA16816(acc[mt][2 * nt2 + 1], ah[mt][0], ah[mt][1], ah[mt][2], ah[mt][3], bl2, bl3);
                    MMA16816(acc[mt][2 * nt2 + 1], al[mt][0], al[mt][1], al[mt][2], al[mt][3], bh2, bh3);
                }
            }
        }
        __syncthreads();
        if (kt + 2 < nkt) G_LOAD(kt + 2, kt & 1);
        CP_COMMIT();
    }

#pragma unroll
    for (int mt = 0; mt < 2; mt++) {
#pragma unroll
        for (int nt = 0; nt < 4; nt++) {
            int row = brow + wm * 32 + mt * 16 + g;
            int col = bcol + wn * 32 + nt * 8 + 2 * q;
            float c0 = acc[mt][nt][0], c1 = acc[mt][nt][1];
            float c2 = acc[mt][nt][2], c3 = acc[mt][nt][3];
            if (Cf) {
                if (bias) { c0 += bias[col]; c1 += bias[col + 1]; c2 += bias[col]; c3 += bias[col + 1]; }
                float2 v0 = {c0, c1}, v1 = {c2, c3};
                *(float2*)&Cf[(size_t)row * ldc + col] = v0;
                *(float2*)&Cf[(size_t)(row + 8) * ldc + col] = v1;
            } else {
                __half h0 = __float2half_rn(c0), h1 = __float2half_rn(c1);
                __half h2 = __float2half_rn(c2), h3 = __float2half_rn(c3);
                __half l0 = __float2half_rn(c0 - __half2float(h0));
                __half l1 = __float2half_rn(c1 - __half2float(h1));
                __half l2 = __float2half_rn(c2 - __half2float(h2));
                __half l3 = __float2half_rn(c3 - __half2float(h3));
                *(__half2*)&Ch[(size_t)row * ldc + col]       = __halves2half2(h0, h1);
                *(__half2*)&Ch[(size_t)(row + 8) * ldc + col] = __halves2half2(h2, h3);
                *(__half2*)&Cl[(size_t)row * ldc + col]       = __halves2half2(l0, l1);
                *(__half2*)&Cl[(size_t)(row + 8) * ldc + col] = __halves2half2(l2, l3);
            }
        }
    }
#undef G_LOAD
}

// ---------------------------------------------------------------------------
// Causal flash attention, split-fp16 MMA, XOR-swizzled smem (no padding).
// 128 q-rows/CTA, 64-key tiles, 8 warps, 256 threads, 2 CTAs/SM.
// smem: Qh[128][64], Ql[128][64], K stages [2][h|l][64][64] = 64KB total.
// Q fragments reloaded from smem each tile (keeps regs < 128).
// ---------------------------------------------------------------------------
#define A_QTILE_B 16384              // 128*64*2
#define A_KTILE_B 8192               // 64*64*2
#define A_KOFF    (2 * A_QTILE_B)    // 32768
#define A_SMEM_B  (A_KOFF + 4 * A_KTILE_B)   // 65536

// swizzled byte offset within a tile: row * 128 + (chunk ^ (row&7)) * 16
#define SWZ(row_, chunk_) ((uint32_t)((row_) * 128 + (((chunk_) ^ ((row_) & 7)) << 4)))

__global__ __launch_bounds__(256, 2) void attn_mma_kernel(
    const __half* __restrict__ Ph, const __half* __restrict__ Pl,
    __half* __restrict__ Oh, __half* __restrict__ Ol)
{
    extern __shared__ char smem[];
    const uint32_t sb = smem_u32(smem);
    const int qt = (gridDim.x - 1) - blockIdx.x;   // heaviest blocks first
    const int h = blockIdx.y, b = blockIdx.z;
    const int tid = threadIdx.x;
    const int lane = tid & 31, wid = tid >> 5;
    const int g = lane >> 2, q = lane & 3;
    const int ml = lane >> 3, rl = lane & 7;

    const size_t pbase = (size_t)b * SEQ * INNER + h * DHEAD;

    // ---- Q prologue: 2 tiles * 128 rows * 8 chunks = 2048 -> 8 per thread ----
#pragma unroll
    for (int i = 0; i < 8; i++) {
        int id = tid + (i << 8);
        int t = id >> 10, row = (id >> 3) & 127, c = id & 7;
        const __half* gp = (t ? Pl : Ph) + pbase + (size_t)(qt * 128 + row) * INNER + (c << 3);
        CP_ASYNC16(sb + t * A_QTILE_B + SWZ(row, c), gp);
    }
    CP_COMMIT();

#define A_LOADK(kt_, s_) do {                                                      \
    _Pragma("unroll")                                                              \
    for (int _i = 0; _i < 4; _i++) {                                               \
        int _id = tid + (_i << 8);                                                 \
        int _t = _id >> 9, _row = (_id >> 3) & 63, _c = _id & 7;                   \
        const __half* _gp = (_t ? Pl : Ph) + pbase                                 \
            + (size_t)((kt_) * 64 + _row) * INNER + (_c << 3);                     \
        CP_ASYNC16(sb + A_KOFF + ((s_) * 2 + _t) * A_KTILE_B + SWZ(_row, _c), _gp);\
    }                                                                              \
} while (0)

    const int ntiles = 2 * qt + 2;
    A_LOADK(0, 0); CP_COMMIT();
    A_LOADK(1, 1); CP_COMMIT();

    float o[8][4];
#pragma unroll
    for (int nt = 0; nt < 8; nt++)
#pragma unroll
        for (int e = 0; e < 4; e++) o[nt][e] = 0.f;
    float m_i[2] = {-1e30f, -1e30f};
    float l_i[2] = {0.f, 0.f};

    // Q fragment base addresses (row/chunk fixed per thread per ks)
    const int qrow_f = wid * 16 + (ml & 1) * 8 + rl;

    for (int kt = 0; kt < ntiles; kt++) {
        CP_WAIT1();
        __syncthreads();
        const uint32_t kh_base = sb + A_KOFF + ((kt & 1) * 2) * A_KTILE_B;
        const uint32_t kl_base = kh_base + A_KTILE_B;

        // ---- S = (Qh+Ql)(Kh+Kl)^T ----
        float s[8][4];
#pragma unroll
        for (int nt = 0; nt < 8; nt++)
#pragma unroll
            for (int e = 0; e < 4; e++) s[nt][e] = 0.f;

#pragma unroll
        for (int ks = 0; ks < 4; ks++) {
            uint32_t qh0, qh1, qh2, qh3, ql0, ql1, ql2, ql3;
            {
                int chunk = ks * 2 + (ml >> 1);
                uint32_t off = SWZ(qrow_f, chunk);
                LDSM4(qh0, qh1, qh2, qh3, sb + off);
                LDSM4(ql0, ql1, ql2, ql3, sb + A_QTILE_B + off);
            }
#pragma unroll
            for (int nt2 = 0; nt2 < 4; nt2++) {
                int br = nt2 * 16 + (ml >> 1) * 8 + rl;
                int bc = ks * 2 + (ml & 1);
                uint32_t off = SWZ(br, bc);
                uint32_t bh0, bh1, bh2, bh3, bl0, bl1, bl2, bl3;
                LDSM4(bh0, bh1, bh2, bh3, kh_base + off);
                LDSM4(bl0, bl1, bl2, bl3, kl_base + off);
                MMA16816(s[2 * nt2],     qh0, qh1, qh2, qh3, bh0, bh1);
                MMA16816(s[2 * nt2],     qh0, qh1, qh2, qh3, bl0, bl1);
                MMA16816(s[2 * nt2],     ql0, ql1, ql2, ql3, bh0, bh1);
                MMA16816(s[2 * nt2 + 1], qh0, qh1, qh2, qh3, bh2, bh3);
                MMA16816(s[2 * nt2 + 1], qh0, qh1, qh2, qh3, bl2, bl3);
                MMA16816(s[2 * nt2 + 1], ql0, ql1, ql2, ql3, bh2, bh3);
            }
        }

        // ---- online softmax ----
        const bool domask = (kt >= 2 * qt);
        const int kbase = kt * 64;
#pragma unroll
        for (int rr = 0; rr < 2; rr++) {
            const int qrow = qt * 128 + wid * 16 + g + rr * 8;
            float mt = -1e30f;
#pragma unroll
            for (int nt = 0; nt < 8; nt++)
#pragma unroll
                for (int e = 0; e < 2; e++) {
                    float v = s[nt][rr * 2 + e] * SSCALE;
                    if (domask && (kbase + nt * 8 + 2 * q + e > qrow)) v = -1e30f;
                    s[nt][rr * 2 + e] = v;
                    mt = fmaxf(mt, v);
                }
            mt = fmaxf(mt, __shfl_xor_sync(0xffffffffu, mt, 1, 4));
            mt = fmaxf(mt, __shfl_xor_sync(0xffffffffu, mt, 2, 4));
            float mnew = fmaxf(m_i[rr], mt);
            float alpha = __expf(m_i[rr] - mnew);
            m_i[rr] = mnew;
            float ls = 0.f;
#pragma unroll
            for (int nt = 0; nt < 8; nt++)
#pragma unroll
                for (int e = 0; e < 2; e++) {
                    float p = __expf(s[nt][rr * 2 + e] - mnew);
                    s[nt][rr * 2 + e] = p;
                    ls += p;
                }
            ls += __shfl_xor_sync(0xffffffffu, ls, 1, 4);
            ls += __shfl_xor_sync(0xffffffffu, ls, 2, 4);
            l_i[rr] = l_i[rr] * alpha + ls;
#pragma unroll
            for (int nt = 0; nt < 8; nt++)
#pragma unroll
                for (int e = 0; e < 2; e++) o[nt][rr * 2 + e] *= alpha;
        }

        // ---- pack probs ----
        uint32_t pa[4][4];
#pragma unroll
        for (int ks = 0; ks < 4; ks++) {
            pa[ks][0] = packh2(s[2 * ks][0],     s[2 * ks][1]);
            pa[ks][1] = packh2(s[2 * ks][2],     s[2 * ks][3]);
            pa[ks][2] = packh2(s[2 * ks + 1][0], s[2 * ks + 1][1]);
            pa[ks][3] = packh2(s[2 * ks + 1][2], s[2 * ks + 1][3]);
        }

        // ---- O += P (Vh + Vl) ----
#pragma unroll
        for (int ks = 0; ks < 4; ks++) {
#pragma unroll
            for (int nt2 = 0; nt2 < 4; nt2++) {
                int vrow = ks * 16 + (ml & 1) * 8 + rl;
                int vchunk = nt2 * 2 + (ml >> 1);
                uint32_t off = SWZ(vrow, vchunk);
                uint32_t vh0, vh1, vh2, vh3, vl0, vl1, vl2, vl3;
                LDSM4T(vh0, vh1, vh2, vh3, kh_base + off);
                LDSM4T(vl0, vl1, vl2, vl3, kl_base + off);
                MMA16816(o[2 * nt2],     pa[ks][0], pa[ks][1], pa[ks][2], pa[ks][3], vh0, vh1);
                MMA16816(o[2 * nt2],     pa[ks][0], pa[ks][1], pa[ks][2], pa[ks][3], vl0, vl1);
                MMA16816(o[2 * nt2 + 1], pa[ks][0], pa[ks][1], pa[ks][2], pa[ks][3], vh2, vh3);
                MMA16816(o[2 * nt2 + 1], pa[ks][0], pa[ks][1], pa[ks][2], pa[ks][3], vl2, vl3);
            }
        }

        __syncthreads();
        if (kt + 2 < ntiles) A_LOADK(kt + 2, kt & 1);
        CP_COMMIT();
    }

    // ---- normalize + split-store ----
#pragma unroll
    for (int rr = 0; rr < 2; rr++) {
        const float inv = 1.f / l_i[rr];
        const size_t row = (size_t)b * SEQ + qt * 128 + wid * 16 + g + rr * 8;
#pragma unroll
        for (int nt = 0; nt < 8; nt++) {
            float v0 = o[nt][rr * 2 + 0] * inv;
            float v1 = o[nt][rr * 2 + 1] * inv;
            __half h0 = __float2half_rn(v0), h1 = __float2half_rn(v1);
            __half l0 = __float2half_rn(v0 - __half2float(h0));
            __half l1 = __float2half_rn(v1 - __half2float(h1));
            size_t idx = row * INNER + h * DHEAD + nt * 8 + 2 * q;
            *(__half2*)&Oh[idx] = __halves2half2(h0, h1);
            *(__half2*)&Ol[idx] = __halves2half2(l0, l1);
        }
    }
#undef A_LOADK
}

// ---------------------------------------------------------------------------
extern "C" void kernel_launch(void* const* d_in, const int* in_sizes, int n_in,
                              void* d_out, int out_size)
{
    const float* x     = (const float*)d_in[0];
    const float* w_qkv = (const float*)d_in[1];
    const float* w_out = (const float*)d_in[2];
    const float* b_out = (const float*)d_in[3];
    float* out = (float*)d_out;

    __half *xh, *xl, *Ph, *Pl, *Ohp, *Olp, *Wqh, *Wql, *Woh, *Wol;
    cudaGetSymbolAddress((void**)&xh, g_xh);   cudaGetSymbolAddress((void**)&xl, g_xl);
    cudaGetSymbolAddress((void**)&Ph, g_Ph);   cudaGetSymbolAddress((void**)&Pl, g_Pl);
    cudaGetSymbolAddress((void**)&Ohp, g_Oh);  cudaGetSymbolAddress((void**)&Olp, g_Ol);
    cudaGetSymbolAddress((void**)&Wqh, g_Wqh); cudaGetSymbolAddress((void**)&Wql, g_Wql);
    cudaGetSymbolAddress((void**)&Woh, g_Woh); cudaGetSymbolAddress((void**)&Wol, g_Wol);

    static int configured = 0;
    if (!configured) {
        cudaFuncSetAttribute(gemm_split_kernel,
                             cudaFuncAttributeMaxDynamicSharedMemorySize, G_SMEM_B);
        cudaFuncSetAttribute(attn_mma_kernel,
                             cudaFuncAttributeMaxDynamicSharedMemorySize, A_SMEM_B);
        configured = 1;
    }

    split_kernel<<<(MTOT * DIM / 4 + 255) / 256, 256>>>(x, xh, xl, MTOT * DIM / 4);
    dim3 tblk(32, 8), tgrd(32, 32);
    transpose_split_kernel<<<tgrd, tblk>>>(w_qkv, Wqh, Wql, 3 * INNER);
    transpose_split_kernel<<<tgrd, tblk>>>(w_out, Woh, Wol, DIM);

    dim3 gblk(256), ggrd(INNER / 64, MTOT / 128);   // (16, 32)
    gemm_split_kernel<<<ggrd, gblk, G_SMEM_B>>>(xh, xl, Wqh, Wql,
                                                nullptr, nullptr, Ph, Pl, DIM, INNER);

    dim3 ablk(256), agrd(SEQ / 128, HEADS, BATCH);
    attn_mma_kernel<<<agrd, ablk, A_SMEM_B>>>(Ph, Pl, Ohp, Olp);

    gemm_split_kernel<<<ggrd, gblk, G_SMEM_B>>>(Ohp, Olp, Woh, Wol,
                                                out, b_out, nullptr, nullptr, INNER, DIM);
}

// round 5
// speedup vs baseline: 2.8733x; 1.0660x over previous
#include <cuda_runtime.h>
#include <cuda_fp16.h>
#include <stdint.h>
#include <math.h>

#define BATCH  2
#define SEQ    2048
#define DIM    1024
#define HEADS  16
#define DHEAD  64
#define INNER  1024
#define MTOT   (BATCH*SEQ)
#define SSCALE 0.125f

// ---------------------------------------------------------------------------
// Device-global scratch (hi/lo fp16 splits)
// ---------------------------------------------------------------------------
__device__ __half g_xh[MTOT * DIM],   g_xl[MTOT * DIM];
__device__ __half g_Ph[MTOT * INNER], g_Pl[MTOT * INNER];
__device__ __half g_Oh[MTOT * INNER], g_Ol[MTOT * INNER];
__device__ __half g_Wqh[INNER * DIM], g_Wql[INNER * DIM];
__device__ __half g_Woh[DIM * INNER], g_Wol[DIM * INNER];

// ---------------------------------------------------------------------------
// PTX helpers (family-portable only)
// ---------------------------------------------------------------------------
__device__ __forceinline__ uint32_t smem_u32(const void* p) {
    uint32_t a;
    asm("{ .reg .u64 t; cvta.to.shared.u64 t, %1; cvt.u32.u64 %0, t; }" : "=r"(a) : "l"(p));
    return a;
}

#define CP_ASYNC16(dst, src) \
    asm volatile("cp.async.cg.shared.global [%0], [%1], 16;" :: "r"(dst), "l"(src) : "memory")
#define CP_COMMIT() asm volatile("cp.async.commit_group;" ::: "memory")
#define CP_WAIT1()  asm volatile("cp.async.wait_group 1;"  ::: "memory")

#define LDSM4(r0, r1, r2, r3, a) \
    asm volatile("ldmatrix.sync.aligned.m8n8.x4.shared.b16 {%0,%1,%2,%3}, [%4];" \
        : "=r"(r0), "=r"(r1), "=r"(r2), "=r"(r3) : "r"(a))
#define LDSM4T(r0, r1, r2, r3, a) \
    asm volatile("ldmatrix.sync.aligned.m8n8.x4.trans.shared.b16 {%0,%1,%2,%3}, [%4];" \
        : "=r"(r0), "=r"(r1), "=r"(r2), "=r"(r3) : "r"(a))

#define MMA16816(d, a0, a1, a2, a3, b0, b1) \
    asm volatile("mma.sync.aligned.m16n8k16.row.col.f32.f16.f16.f32 " \
        "{%0,%1,%2,%3}, {%4,%5,%6,%7}, {%8,%9}, {%0,%1,%2,%3};" \
        : "+f"((d)[0]), "+f"((d)[1]), "+f"((d)[2]), "+f"((d)[3]) \
        : "r"(a0), "r"(a1), "r"(a2), "r"(a3), "r"(b0), "r"(b1))

__device__ __forceinline__ uint32_t packh2(float lo, float hi) {
    __half2 h = __floats2half2_rn(lo, hi);
    return *reinterpret_cast<uint32_t*>(&h);
}

// ---------------------------------------------------------------------------
// fp32 -> (fp16 hi, fp16 lo) split
// ---------------------------------------------------------------------------
__global__ __launch_bounds__(256) void split_kernel(
    const float* __restrict__ in, __half* __restrict__ hi, __half* __restrict__ lo, int n4)
{
    int i = blockIdx.x * 256 + threadIdx.x;
    if (i >= n4) return;
    float4 v = ((const float4*)in)[i];
    __half hx = __float2half_rn(v.x), hy = __float2half_rn(v.y);
    __half hz = __float2half_rn(v.z), hw = __float2half_rn(v.w);
    __half lx = __float2half_rn(v.x - __half2float(hx));
    __half ly = __float2half_rn(v.y - __half2float(hy));
    __half lz = __float2half_rn(v.z - __half2float(hz));
    __half lw = __float2half_rn(v.w - __half2float(hw));
    ((__half2*)hi)[2 * i]     = __halves2half2(hx, hy);
    ((__half2*)hi)[2 * i + 1] = __halves2half2(hz, hw);
    ((__half2*)lo)[2 * i]     = __halves2half2(lx, ly);
    ((__half2*)lo)[2 * i + 1] = __halves2half2(lz, lw);
}

// ---------------------------------------------------------------------------
// Transpose + split
// ---------------------------------------------------------------------------
__global__ __launch_bounds__(256) void transpose_split_kernel(
    const float* __restrict__ src, __half* __restrict__ dh, __half* __restrict__ dl, int ld_src)
{
    __shared__ float t[32][33];
    int bx = blockIdx.x * 32;
    int by = blockIdx.y * 32;
    int x = threadIdx.x, y0 = threadIdx.y;
#pragma unroll
    for (int i = 0; i < 32; i += 8)
        t[y0 + i][x] = src[(size_t)(by + y0 + i) * ld_src + bx + x];
    __syncthreads();
#pragma unroll
    for (int i = 0; i < 32; i += 8) {
        float v = t[x][y0 + i];
        __half h = __float2half_rn(v);
        __half l = __float2half_rn(v - __half2float(h));
        size_t idx = (size_t)(bx + y0 + i) * 1024 + by + x;
        dh[idx] = h;
        dl[idx] = l;
    }
}

// ---------------------------------------------------------------------------
// Split-fp16 MMA GEMM: C = (Ah+Al) @ (Bh+Bl)^T   (B stored [N][K])
// BM=128, BN=128, BK=32, 256 thr (8 warps: 4m x 2n, warp tile 32x64).
// 2-stage cp.async, 2 CTAs/SM. smem rows padded to 40 halfs (80B).
// ---------------------------------------------------------------------------
#define G_TILE_B  10240               // 128*40*2
#define G_STAGE_B (4 * G_TILE_B)      // Ah Al Bh Bl = 40960
#define G_SMEM_B  (2 * G_STAGE_B)     // 81920

__global__ __launch_bounds__(256, 2) void gemm_split_kernel(
    const __half* __restrict__ Ah, const __half* __restrict__ Al,
    const __half* __restrict__ Bh, const __half* __restrict__ Bl,
    float* __restrict__ Cf, const float* __restrict__ bias,
    __half* __restrict__ Ch, __half* __restrict__ Cl,
    int K, int ldc)
{
    extern __shared__ char smem[];
    const uint32_t sb = smem_u32(smem);
    const int tid = threadIdx.x;
    const int lane = tid & 31, wid = tid >> 5;
    const int g = lane >> 2, q = lane & 3;
    const int ml = lane >> 3, rl = lane & 7;
    const int wm = wid >> 1, wn = wid & 1;
    const int brow = blockIdx.y * 128;
    const int bcol = blockIdx.x * 128;

    float acc[2][8][4];
#pragma unroll
    for (int a = 0; a < 2; a++)
#pragma unroll
        for (int b = 0; b < 8; b++)
#pragma unroll
            for (int c = 0; c < 4; c++) acc[a][b][c] = 0.f;

    // per stage: 4 tiles * 128 rows * 4 chunks = 2048 -> 8 per thread
#define G_LOAD(kt_, s_) do {                                                       \
    int _k0 = (kt_) << 5;                                                          \
    _Pragma("unroll")                                                              \
    for (int _i = 0; _i < 8; _i++) {                                               \
        int _id = tid + (_i << 8);                                                 \
        int _t = _id >> 9, _row = (_id >> 2) & 127, _c = _id & 3;                  \
        const __half* _src = (_t == 0) ? Ah : (_t == 1) ? Al : (_t == 2) ? Bh : Bl;\
        int _grow = ((_t < 2) ? brow : bcol) + _row;                               \
        uint32_t _dst = sb + (s_) * G_STAGE_B + _t * G_TILE_B + _row * 80 + (_c << 4); \
        CP_ASYNC16(_dst, _src + (size_t)_grow * K + _k0 + (_c << 3));              \
    }                                                                              \
} while (0)

    G_LOAD(0, 0); CP_COMMIT();
    G_LOAD(1, 1); CP_COMMIT();

    const int nkt = K >> 5;
    for (int kt = 0; kt < nkt; kt++) {
        CP_WAIT1();
        __syncthreads();
        const uint32_t base = sb + (kt & 1) * G_STAGE_B;

#pragma unroll
        for (int ks = 0; ks < 2; ks++) {
            const int kk = ks << 4;
            uint32_t ah[2][4], al[2][4];
#pragma unroll
            for (int mt = 0; mt < 2; mt++) {
                int arow = wm * 32 + mt * 16 + (ml & 1) * 8 + rl;
                int acol = kk + (ml >> 1) * 8;
                uint32_t off = (uint32_t)(arow * 40 + acol) * 2;
                LDSM4(ah[mt][0], ah[mt][1], ah[mt][2], ah[mt][3], base + off);
                LDSM4(al[mt][0], al[mt][1], al[mt][2], al[mt][3], base + G_TILE_B + off);
            }
#pragma unroll
            for (int nt2 = 0; nt2 < 4; nt2++) {
                int br = wn * 64 + nt2 * 16 + (ml >> 1) * 8 + rl;
                int bc = kk + (ml & 1) * 8;
                uint32_t off = (uint32_t)(br * 40 + bc) * 2;
                uint32_t bh0, bh1, bh2, bh3, bl0, bl1, bl2, bl3;
                LDSM4(bh0, bh1, bh2, bh3, base + 2 * G_TILE_B + off);
                LDSM4(bl0, bl1, bl2, bl3, base + 3 * G_TILE_B + off);
#pragma unroll
                for (int mt = 0; mt < 2; mt++) {
                    MMA16816(acc[mt][2 * nt2],     ah[mt][0], ah[mt][1], ah[mt][2], ah[mt][3], bh0, bh1);
                    MMA16816(acc[mt][2 * nt2],     ah[mt][0], ah[mt][1], ah[mt][2], ah[mt][3], bl0, bl1);
                    MMA16816(acc[mt][2 * nt2],     al[mt][0], al[mt][1], al[mt][2], al[mt][3], bh0, bh1);
                    MMA16816(acc[mt][2 * nt2 + 1], ah[mt][0], ah[mt][1], ah[mt][2], ah[mt][3], bh2, bh3);
                    MMA16816(acc[mt][2 * nt2 + 1], ah[mt][0], ah[mt][1], ah[mt][2], ah[mt][3], bl2, bl3);
                    MMA16816(acc[mt][2 * nt2 + 1], al[mt][0], al[mt][1], al[mt][2], al[mt][3], bh2, bh3);
                }
            }
        }
        __syncthreads();
        if (kt + 2 < nkt) G_LOAD(kt + 2, kt & 1);
        CP_COMMIT();
    }

#pragma unroll
    for (int mt = 0; mt < 2; mt++) {
#pragma unroll
        for (int nt = 0; nt < 8; nt++) {
            int row = brow + wm * 32 + mt * 16 + g;
            int col = bcol + wn * 64 + nt * 8 + 2 * q;
            float c0 = acc[mt][nt][0], c1 = acc[mt][nt][1];
            float c2 = acc[mt][nt][2], c3 = acc[mt][nt][3];
            if (Cf) {
                if (bias) { c0 += bias[col]; c1 += bias[col + 1]; c2 += bias[col]; c3 += bias[col + 1]; }
                float2 v0 = {c0, c1}, v1 = {c2, c3};
                *(float2*)&Cf[(size_t)row * ldc + col] = v0;
                *(float2*)&Cf[(size_t)(row + 8) * ldc + col] = v1;
            } else {
                __half h0 = __float2half_rn(c0), h1 = __float2half_rn(c1);
                __half h2 = __float2half_rn(c2), h3 = __float2half_rn(c3);
                __half l0 = __float2half_rn(c0 - __half2float(h0));
                __half l1 = __float2half_rn(c1 - __half2float(h1));
                __half l2 = __float2half_rn(c2 - __half2float(h2));
                __half l3 = __float2half_rn(c3 - __half2float(h3));
                *(__half2*)&Ch[(size_t)row * ldc + col]       = __halves2half2(h0, h1);
                *(__half2*)&Ch[(size_t)(row + 8) * ldc + col] = __halves2half2(h2, h3);
                *(__half2*)&Cl[(size_t)row * ldc + col]       = __halves2half2(l0, l1);
                *(__half2*)&Cl[(size_t)(row + 8) * ldc + col] = __halves2half2(l2, l3);
            }
        }
    }
#undef G_LOAD
}

// ---------------------------------------------------------------------------
// Causal flash attention, split-fp16 MMA, XOR-swizzled smem.
// 128 q-rows/CTA, 4 warps x 32 q-rows, 128 threads, 2 CTAs/SM.
// smem: Qh/Ql [128][64], K stages [2][h|l][64][64] = 64KB.
// ---------------------------------------------------------------------------
#define A_QTILE_B 16384              // 128*64*2
#define A_KTILE_B 8192               // 64*64*2
#define A_KOFF    (2 * A_QTILE_B)    // 32768
#define A_SMEM_B  (A_KOFF + 4 * A_KTILE_B)   // 65536

#define SWZ(row_, chunk_) ((uint32_t)((row_) * 128 + (((chunk_) ^ ((row_) & 7)) << 4)))

__global__ __launch_bounds__(128, 2) void attn_mma_kernel(
    const __half* __restrict__ Ph, const __half* __restrict__ Pl,
    __half* __restrict__ Oh, __half* __restrict__ Ol)
{
    extern __shared__ char smem[];
    const uint32_t sb = smem_u32(smem);
    const int qt = (gridDim.x - 1) - blockIdx.x;   // heaviest first
    const int h = blockIdx.y, b = blockIdx.z;
    const int tid = threadIdx.x;
    const int lane = tid & 31, wid = tid >> 5;     // 4 warps
    const int g = lane >> 2, q = lane & 3;
    const int ml = lane >> 3, rl = lane & 7;

    const size_t pbase = (size_t)b * SEQ * INNER + h * DHEAD;

    // ---- Q prologue: 2 tiles * 128 rows * 8 chunks = 2048 -> 16/thread ----
#pragma unroll
    for (int i = 0; i < 16; i++) {
        int id = tid + (i << 7);
        int t = id >> 10, row = (id >> 3) & 127, c = id & 7;
        const __half* gp = (t ? Pl : Ph) + pbase + (size_t)(qt * 128 + row) * INNER + (c << 3);
        CP_ASYNC16(sb + t * A_QTILE_B + SWZ(row, c), gp);
    }
    CP_COMMIT();

#define A_LOADK(kt_, s_) do {                                                      \
    _Pragma("unroll")                                                              \
    for (int _i = 0; _i < 8; _i++) {  /* 2*64*8 = 1024 chunks */                   \
        int _id = tid + (_i << 7);                                                 \
        int _t = _id >> 9, _row = (_id >> 3) & 63, _c = _id & 7;                   \
        const __half* _gp = (_t ? Pl : Ph) + pbase                                 \
            + (size_t)((kt_) * 64 + _row) * INNER + (_c << 3);                     \
        CP_ASYNC16(sb + A_KOFF + ((s_) * 2 + _t) * A_KTILE_B + SWZ(_row, _c), _gp);\
    }                                                                              \
} while (0)

    const int ntiles = 2 * qt + 2;
    A_LOADK(0, 0); CP_COMMIT();
    A_LOADK(1, 1); CP_COMMIT();

    float o[2][8][4];
#pragma unroll
    for (int mt = 0; mt < 2; mt++)
#pragma unroll
        for (int nt = 0; nt < 8; nt++)
#pragma unroll
            for (int e = 0; e < 4; e++) o[mt][nt][e] = 0.f;
    float m_i[4] = {-1e30f, -1e30f, -1e30f, -1e30f};
    float l_i[4] = {0.f, 0.f, 0.f, 0.f};

    for (int kt = 0; kt < ntiles; kt++) {
        CP_WAIT1();
        __syncthreads();
        const uint32_t kh_base = sb + A_KOFF + ((kt & 1) * 2) * A_KTILE_B;
        const uint32_t kl_base = kh_base + A_KTILE_B;

        // ---- S = (Qh+Ql)(Kh+Kl)^T, warp covers 32 q-rows x 64 keys ----
        float s[2][8][4];
#pragma unroll
        for (int mt = 0; mt < 2; mt++)
#pragma unroll
            for (int nt = 0; nt < 8; nt++)
#pragma unroll
                for (int e = 0; e < 4; e++) s[mt][nt][e] = 0.f;

#pragma unroll
        for (int ks = 0; ks < 4; ks++) {
            uint32_t qh[2][4], ql[2][4];
#pragma unroll
            for (int mt = 0; mt < 2; mt++) {
                int qrow = wid * 32 + mt * 16 + (ml & 1) * 8 + rl;
                int chunk = ks * 2 + (ml >> 1);
                uint32_t off = SWZ(qrow, chunk);
                LDSM4(qh[mt][0], qh[mt][1], qh[mt][2], qh[mt][3], sb + off);
                LDSM4(ql[mt][0], ql[mt][1], ql[mt][2], ql[mt][3], sb + A_QTILE_B + off);
            }
#pragma unroll
            for (int nt2 = 0; nt2 < 4; nt2++) {
                int br = nt2 * 16 + (ml >> 1) * 8 + rl;
                int bc = ks * 2 + (ml & 1);
                uint32_t off = SWZ(br, bc);
                uint32_t bh0, bh1, bh2, bh3, bl0, bl1, bl2, bl3;
                LDSM4(bh0, bh1, bh2, bh3, kh_base + off);
                LDSM4(bl0, bl1, bl2, bl3, kl_base + off);
#pragma unroll
                for (int mt = 0; mt < 2; mt++) {
                    MMA16816(s[mt][2 * nt2],     qh[mt][0], qh[mt][1], qh[mt][2], qh[mt][3], bh0, bh1);
                    MMA16816(s[mt][2 * nt2],     qh[mt][0], qh[mt][1], qh[mt][2], qh[mt][3], bl0, bl1);
                    MMA16816(s[mt][2 * nt2],     ql[mt][0], ql[mt][1], ql[mt][2], ql[mt][3], bh0, bh1);
                    MMA16816(s[mt][2 * nt2 + 1], qh[mt][0], qh[mt][1], qh[mt][2], qh[mt][3], bh2, bh3);
                    MMA16816(s[mt][2 * nt2 + 1], qh[mt][0], qh[mt][1], qh[mt][2], qh[mt][3], bl2, bl3);
                    MMA16816(s[mt][2 * nt2 + 1], ql[mt][0], ql[mt][1], ql[mt][2], ql[mt][3], bh2, bh3);
                }
            }
        }

        // ---- online softmax (4 row-groups per lane: mt x {g, g+8}) ----
        const bool domask = (kt >= 2 * qt);
        const int kbase = kt * 64;
#pragma unroll
        for (int mt = 0; mt < 2; mt++) {
#pragma unroll
            for (int half = 0; half < 2; half++) {
                const int rr = mt * 2 + half;
                const int qrow = qt * 128 + wid * 32 + mt * 16 + g + half * 8;
                float mt_ = -1e30f;
#pragma unroll
                for (int nt = 0; nt < 8; nt++)
#pragma unroll
                    for (int e = 0; e < 2; e++) {
                        float v = s[mt][nt][half * 2 + e] * SSCALE;
                        if (domask && (kbase + nt * 8 + 2 * q + e > qrow)) v = -1e30f;
                        s[mt][nt][half * 2 + e] = v;
                        mt_ = fmaxf(mt_, v);
                    }
                mt_ = fmaxf(mt_, __shfl_xor_sync(0xffffffffu, mt_, 1, 4));
                mt_ = fmaxf(mt_, __shfl_xor_sync(0xffffffffu, mt_, 2, 4));
                float mnew = fmaxf(m_i[rr], mt_);
                float alpha = __expf(m_i[rr] - mnew);
                m_i[rr] = mnew;
                float ls = 0.f;
#pragma unroll
                for (int nt = 0; nt < 8; nt++)
#pragma unroll
                    for (int e = 0; e < 2; e++) {
                        float p = __expf(s[mt][nt][half * 2 + e] - mnew);
                        s[mt][nt][half * 2 + e] = p;
                        ls += p;
                    }
                ls += __shfl_xor_sync(0xffffffffu, ls, 1, 4);
                ls += __shfl_xor_sync(0xffffffffu, ls, 2, 4);
                l_i[rr] = l_i[rr] * alpha + ls;
#pragma unroll
                for (int nt = 0; nt < 8; nt++)
#pragma unroll
                    for (int e = 0; e < 2; e++) o[mt][nt][half * 2 + e] *= alpha;
            }
        }

        // ---- pack probs ----
        uint32_t pa[2][4][4];
#pragma unroll
        for (int mt = 0; mt < 2; mt++)
#pragma unroll
            for (int ks = 0; ks < 4; ks++) {
                pa[mt][ks][0] = packh2(s[mt][2 * ks][0],     s[mt][2 * ks][1]);
                pa[mt][ks][1] = packh2(s[mt][2 * ks][2],     s[mt][2 * ks][3]);
                pa[mt][ks][2] = packh2(s[mt][2 * ks + 1][0], s[mt][2 * ks + 1][1]);
                pa[mt][ks][3] = packh2(s[mt][2 * ks + 1][2], s[mt][2 * ks + 1][3]);
            }

        // ---- O += P (Vh + Vl) ----
#pragma unroll
        for (int ks = 0; ks < 4; ks++) {
#pragma unroll
            for (int nt2 = 0; nt2 < 4; nt2++) {
                int vrow = ks * 16 + (ml & 1) * 8 + rl;
                int vchunk = nt2 * 2 + (ml >> 1);
                uint32_t off = SWZ(vrow, vchunk);
                uint32_t vh0, vh1, vh2, vh3, vl0, vl1, vl2, vl3;
                LDSM4T(vh0, vh1, vh2, vh3, kh_base + off);
                LDSM4T(vl0, vl1, vl2, vl3, kl_base + off);
#pragma unroll
                for (int mt = 0; mt < 2; mt++) {
                    MMA16816(o[mt][2 * nt2],     pa[mt][ks][0], pa[mt][ks][1], pa[mt][ks][2], pa[mt][ks][3], vh0, vh1);
                    MMA16816(o[mt][2 * nt2],     pa[mt][ks][0], pa[mt][ks][1], pa[mt][ks][2], pa[mt][ks][3], vl0, vl1);
                    MMA16816(o[mt][2 * nt2 + 1], pa[mt][ks][0], pa[mt][ks][1], pa[mt][ks][2], pa[mt][ks][3], vh2, vh3);
                    MMA16816(o[mt][2 * nt2 + 1], pa[mt][ks][0], pa[mt][ks][1], pa[mt][ks][2], pa[mt][ks][3], vl2, vl3);
                }
            }
        }

        __syncthreads();
        if (kt + 2 < ntiles) A_LOADK(kt + 2, kt & 1);
        CP_COMMIT();
    }

    // ---- normalize + split-store ----
#pragma unroll
    for (int mt = 0; mt < 2; mt++) {
#pragma unroll
        for (int half = 0; half < 2; half++) {
            const int rr = mt * 2 + half;
            const float inv = 1.f / l_i[rr];
            const size_t row = (size_t)b * SEQ + qt * 128 + wid * 32 + mt * 16 + g + half * 8;
#pragma unroll
            for (int nt = 0; nt < 8; nt++) {
                float v0 = o[mt][nt][half * 2 + 0] * inv;
                float v1 = o[mt][nt][half * 2 + 1] * inv;
                __half h0 = __float2half_rn(v0), h1 = __float2half_rn(v1);
                __half l0 = __float2half_rn(v0 - __half2float(h0));
                __half l1 = __float2half_rn(v1 - __half2float(h1));
                size_t idx = row * INNER + h * DHEAD + nt * 8 + 2 * q;
                *(__half2*)&Oh[idx] = __halves2half2(h0, h1);
                *(__half2*)&Ol[idx] = __halves2half2(l0, l1);
            }
        }
    }
#undef A_LOADK
}

// ---------------------------------------------------------------------------
extern "C" void kernel_launch(void* const* d_in, const int* in_sizes, int n_in,
                              void* d_out, int out_size)
{
    const float* x     = (const float*)d_in[0];
    const float* w_qkv = (const float*)d_in[1];
    const float* w_out = (const float*)d_in[2];
    const float* b_out = (const float*)d_in[3];
    float* out = (float*)d_out;

    __half *xh, *xl, *Ph, *Pl, *Ohp, *Olp, *Wqh, *Wql, *Woh, *Wol;
    cudaGetSymbolAddress((void**)&xh, g_xh);   cudaGetSymbolAddress((void**)&xl, g_xl);
    cudaGetSymbolAddress((void**)&Ph, g_Ph);   cudaGetSymbolAddress((void**)&Pl, g_Pl);
    cudaGetSymbolAddress((void**)&Ohp, g_Oh);  cudaGetSymbolAddress((void**)&Olp, g_Ol);
    cudaGetSymbolAddress((void**)&Wqh, g_Wqh); cudaGetSymbolAddress((void**)&Wql, g_Wql);
    cudaGetSymbolAddress((void**)&Woh, g_Woh); cudaGetSymbolAddress((void**)&Wol, g_Wol);

    static int configured = 0;
    if (!configured) {
        cudaFuncSetAttribute(gemm_split_kernel,
                             cudaFuncAttributeMaxDynamicSharedMemorySize, G_SMEM_B);
        cudaFuncSetAttribute(attn_mma_kernel,
                             cudaFuncAttributeMaxDynamicSharedMemorySize, A_SMEM_B);
        configured = 1;
    }

    split_kernel<<<(MTOT * DIM / 4 + 255) / 256, 256>>>(x, xh, xl, MTOT * DIM / 4);
    dim3 tblk(32, 8), tgrd(32, 32);
    transpose_split_kernel<<<tgrd, tblk>>>(w_qkv, Wqh, Wql, 3 * INNER);
    transpose_split_kernel<<<tgrd, tblk>>>(w_out, Woh, Wol, DIM);

    dim3 gblk(256), ggrd(INNER / 128, MTOT / 128);   // (8, 32)
    gemm_split_kernel<<<ggrd, gblk, G_SMEM_B>>>(xh, xl, Wqh, Wql,
                                                nullptr, nullptr, Ph, Pl, DIM, INNER);

    dim3 ablk(128), agrd(SEQ / 128, HEADS, BATCH);
    attn_mma_kernel<<<agrd, ablk, A_SMEM_B>>>(Ph, Pl, Ohp, Olp);

    gemm_split_kernel<<<ggrd, gblk, G_SMEM_B>>>(Ohp, Olp, Woh, Wol,
                                                out, b_out, nullptr, nullptr, INNER, DIM);
}